// round 15
// baseline (speedup 1.0000x reference)
#include <cuda_runtime.h>
#include <cstdint>

// Fused adapter: out = x + 0.1f * ( relu( LN(x) @ Wd + bd ) @ Wu + bu )
// x: [32768, 768] fp32.  Wd: [768,16], Wu: [16,768].
//
// R15: tf32 tensor-core kernel (R14 phases verbatim), reorganized into
// TWO SYMMETRIC TEAMS of 8 warps. Each team owns a private batch stream,
// x_s buffer, dpart/dnf/stats and one named barrier, and runs the full
// pipeline: stage+LN stats -> down MMA (kslice/warp) -> combine+relu ->
// up MMA + epilogue. Teams are fully independent -> barrier bubbles of
// one team are filled by the other (2 warps of each team per SMSP).

#define D_MODEL  768
#define NROWS    32768
#define NTHREADS 512
#define RB       16
#define GRID     152
#define NBATCH   (NROWS / RB)    // 2048
#define NSTREAM  (GRID * 2)      // 304 team-streams

#define XS_STRIDE 772            // 768 + 4 pad: conflict-free A-fragment LDS
#define XS_BUF    (RB * XS_STRIDE)

// smem float offsets (two team buffers where [2] appears)
#define OFF_XS   0                      // 2 * 12352 = 24704
#define OFF_WDF  24704                  // 192 frags * 64 = 12288 (tf32 bits)
#define OFF_WUF  36992                  // 12288
#define OFF_DP   49280                  // 2 * 2048 = 4096
#define OFF_DNF  53376                  // 2 * 256 = 512
#define OFF_STT  53888                  // 2 * 32 = 64
#define OFF_G    53952                  // 16
#define OFF_CB   53968                  // 16
#define OFF_BU   53984                  // 768
#define SMEM_FLOATS 54752
#define SMEM_BYTES  (SMEM_FLOATS * 4)   // 219008 B

#define BAR_SYNC(id, n)   asm volatile("bar.sync %0, %1;" :: "r"(id), "r"(n) : "memory")

__device__ __forceinline__ float shx(float v, int off) {
    return __shfl_xor_sync(0xFFFFFFFFu, v, off);
}
__device__ __forceinline__ float bfly(float a, float b, bool hi, int off) {
    const float keep = hi ? b : a;
    const float send = hi ? a : b;
    return keep + shx(send, off);
}
__device__ __forceinline__ uint32_t f2tf(float f) {
    uint32_t r; asm("cvt.rna.tf32.f32 %0, %1;" : "=r"(r) : "f"(f)); return r;
}
__device__ __forceinline__ void mma8(float& d0, float& d1, float& d2, float& d3,
                                     uint32_t a0, uint32_t a1, uint32_t a2, uint32_t a3,
                                     uint32_t b0, uint32_t b1) {
    asm volatile(
        "mma.sync.aligned.m16n8k8.row.col.f32.tf32.tf32.f32 "
        "{%0,%1,%2,%3}, {%4,%5,%6,%7}, {%8,%9}, {%0,%1,%2,%3};"
        : "+f"(d0), "+f"(d1), "+f"(d2), "+f"(d3)
        : "r"(a0), "r"(a1), "r"(a2), "r"(a3), "r"(b0), "r"(b1));
}

__global__ __launch_bounds__(NTHREADS, 1)
void adapter_fused_kernel(const float* __restrict__ x,
                          const float* __restrict__ ln_g,
                          const float* __restrict__ ln_b,
                          const float* __restrict__ wd,   // [768][16]
                          const float* __restrict__ bd,   // [16]
                          const float* __restrict__ wu,   // [16][768]
                          const float* __restrict__ bu,   // [768]
                          float* __restrict__ out)
{
    extern __shared__ __align__(16) float smp[];

    const int t    = threadIdx.x;
    const int lane = t & 31;
    const int wid  = t >> 5;
    const bool hi16 = (lane & 16) != 0;
    const bool hi8  = (lane & 8)  != 0;
    const bool hi4  = (lane & 4)  != 0;
    const bool hi2  = (lane & 2)  != 0;

    // ===================== init (once per block, all 512) =====================
    if (t < 16) { smp[OFF_G + t] = 0.0f; smp[OFF_CB + t] = bd[t]; }
    __syncthreads();

    if (t < 256) {
        float pg[16], pb[16];
#pragma unroll
        for (int k = 0; k < 16; k++) { pg[k] = 0.0f; pb[k] = 0.0f; }
#pragma unroll
        for (int j = 0; j < 3; j++) {
            const int d = t + 256 * j;
            const float gd = ln_g[d], bdv = ln_b[d];
#pragma unroll
            for (int k = 0; k < 16; k++) {
                const float wv = wd[d * 16 + k];
                pg[k] = fmaf(gd,  wv, pg[k]);
                pb[k] = fmaf(bdv, wv, pb[k]);
            }
        }
#pragma unroll
        for (int which = 0; which < 2; which++) {
            float* v = which ? pb : pg;
            float a8[8], b4[4], c2[2];
#pragma unroll
            for (int j = 0; j < 8; j++) a8[j] = bfly(v[j], v[j + 8], hi16, 16);
#pragma unroll
            for (int j = 0; j < 4; j++) b4[j] = bfly(a8[j], a8[j + 4], hi8, 8);
#pragma unroll
            for (int j = 0; j < 2; j++) c2[j] = bfly(b4[j], b4[j + 2], hi4, 4);
            float z = bfly(c2[0], c2[1], hi2, 2);
            z += shx(z, 1);
            if (!(lane & 1)) {
                if (which) atomicAdd(&smp[OFF_CB + (lane >> 1)], z);
                else       atomicAdd(&smp[OFF_G  + (lane >> 1)], z);
            }
        }
    }

    // B-fragment swizzle (tf32): gamma-folded Wd + Wu
    {
        uint32_t* wdfw = reinterpret_cast<uint32_t*>(smp + OFF_WDF);
        uint32_t* wufw = reinterpret_cast<uint32_t*>(smp + OFF_WUF);
        for (int fi = wid; fi < 192; fi += 16) {
            {   // down B: frag fi = kstep*2 + ntile
                const int s = fi >> 1, nt = fi & 1;
                const int d0 = 8 * s + (lane & 3), d1 = d0 + 4;
                const int kb = 8 * nt + (lane >> 2);
                wdfw[fi * 64 + 2 * lane]     = f2tf(ln_g[d0] * wd[d0 * 16 + kb]);
                wdfw[fi * 64 + 2 * lane + 1] = f2tf(ln_g[d1] * wd[d1 * 16 + kb]);
            }
            {   // up B: frag fi = kstep*96 + ntile
                const int s = fi / 96, nt = fi % 96;
                const int k0 = 8 * s + (lane & 3), k1 = k0 + 4;
                const int d = 8 * nt + (lane >> 2);
                wufw[fi * 64 + 2 * lane]     = f2tf(wu[k0 * D_MODEL + d]);
                wufw[fi * 64 + 2 * lane + 1] = f2tf(wu[k1 * D_MODEL + d]);
            }
        }
    }
    for (int d = t; d < D_MODEL; d += NTHREADS) smp[OFF_BU + d] = bu[d];
    __syncthreads();

    // ===================== team pipeline =====================
    const int team = wid >> 3;        // 0 or 1
    const int tw   = wid & 7;         // warp within team (0..7)
    const int tt   = t & 255;         // thread within team (0..255)
    const int BID  = 1 + team;        // team barrier id

    float* xsb  = smp + OFF_XS  + team * XS_BUF;
    float* dpb  = smp + OFF_DP  + team * 2048;
    float* dnfb = smp + OFF_DNF + team * 256;
    float* sttb = smp + OFF_STT + team * 32;
    const uint32_t* wdfw = reinterpret_cast<const uint32_t*>(smp + OFF_WDF);
    const uint32_t* wufw = reinterpret_cast<const uint32_t*>(smp + OFF_WUF);

    float4 xc4[2][6];   // this warp's 2 rows of the NEXT batch to stage

    auto pref = [&](int bb) {
#pragma unroll
        for (int rr = 0; rr < 2; rr++) {
            const float4* xp = reinterpret_cast<const float4*>(
                x + (bb * RB + 2 * tw + rr) * D_MODEL);
#pragma unroll
            for (int i = 0; i < 6; i++) xc4[rr][i] = xp[lane + 32 * i];
        }
    };

    int b = blockIdx.x * 2 + team;    // team-stream start (0..303)
    pref(b);

    while (b < NBATCH) {
        // -- phase 1: stage x (fp32) + per-row LN stats --
#pragma unroll
        for (int rr = 0; rr < 2; rr++) {
            const int row = 2 * tw + rr;
            float* xd = xsb + row * XS_STRIDE;
            float ss = 0.0f, qq = 0.0f;
#pragma unroll
            for (int i = 0; i < 6; i++) {
                const float4 v = xc4[rr][i];
                *reinterpret_cast<float4*>(xd + 4 * (lane + 32 * i)) = v;
                ss += (v.x + v.y) + (v.z + v.w);
                qq = fmaf(v.x, v.x, fmaf(v.y, v.y,
                     fmaf(v.z, v.z, fmaf(v.w, v.w, qq))));
            }
            float m = bfly(ss, qq, hi16, 16);
            m += shx(m, 8); m += shx(m, 4); m += shx(m, 2); m += shx(m, 1);
            const float q0 = shx(m, 16);
            if (lane == 0) {
                const float mean = m * (1.0f / D_MODEL);
                const float var  = q0 * (1.0f / D_MODEL) - mean * mean;
                *reinterpret_cast<float2*>(sttb + row * 2)
                    = make_float2(mean, rsqrtf(var + 1e-5f));
            }
        }
        const int bn = b + NSTREAM;
        if (bn < NBATCH) pref(bn);    // LDG latency hidden by phases 2-4
        BAR_SYNC(BID, 256);

        // -- phase 2: down MMA, kslice tw (ksteps 12tw..12tw+11), 2 n-tiles --
        {
            const float* a00 = xsb + (lane >> 2) * XS_STRIDE + (lane & 3);
            const float* a10 = a00 + 8 * XS_STRIDE;
            float c00 = 0, c01 = 0, c02 = 0, c03 = 0;
            float c10 = 0, c11 = 0, c12 = 0, c13 = 0;
#pragma unroll
            for (int i = 0; i < 12; i++) {
                const int ks = tw * 12 + i;
                const uint32_t A0 = __float_as_uint(a00[8 * ks]);
                const uint32_t A2 = __float_as_uint(a00[8 * ks + 4]);
                const uint32_t A1 = __float_as_uint(a10[8 * ks]);
                const uint32_t A3 = __float_as_uint(a10[8 * ks + 4]);
                const uint2 b0 = *reinterpret_cast<const uint2*>(
                    wdfw + (ks * 2 + 0) * 64 + 2 * lane);
                const uint2 b1 = *reinterpret_cast<const uint2*>(
                    wdfw + (ks * 2 + 1) * 64 + 2 * lane);
                mma8(c00, c01, c02, c03, A0, A1, A2, A3, b0.x, b0.y);
                mma8(c10, c11, c12, c13, A0, A1, A2, A3, b1.x, b1.y);
            }
            *reinterpret_cast<float4*>(dpb + (tw * 2 + 0) * 128 + lane * 4)
                = make_float4(c00, c01, c02, c03);
            *reinterpret_cast<float4*>(dpb + (tw * 2 + 1) * 128 + lane * 4)
                = make_float4(c10, c11, c12, c13);
        }
        BAR_SYNC(BID, 256);

        // -- phase 3: combine 8 kslice partials + LN correction + relu ->
        //             dnf in up-A-fragment order. Element e = tt: (r, cB). --
        {
            const int r = tt >> 4, cB = tt & 15;
            const float2 st = *reinterpret_cast<const float2*>(sttb + r * 2);
            const int tidf = (r & 7) * 4 + ((cB & 7) >> 1);
            const int reg  = (cB & 1) + 2 * (r >> 3);
            const float* dpp = dpb + (cB >> 3) * 128 + tidf * 4 + reg;
            float P = 0.0f;
#pragma unroll
            for (int ks = 0; ks < 8; ks++) P += dpp[ks * 256];
            float dv = st.y * (P - st.x * smp[OFF_G + cB]) + smp[OFF_CB + cB];
            dv = fmaxf(dv, 0.0f);
            const int sU = cB >> 3;
            const int tA = (r & 7) * 4 + (cB & 3);
            const int j  = (r >> 3) + 2 * ((cB >> 2) & 1);
            dnfb[sU * 128 + tA * 4 + j] = dv;
        }
        BAR_SYNC(BID, 256);

        // -- phase 4: up MMA over 12 n-tiles + epilogue --
        {
            const uint4 A0 = *reinterpret_cast<const uint4*>(dnfb + lane * 4);
            const uint4 A1 = *reinterpret_cast<const uint4*>(dnfb + 128 + lane * 4);
            const int rr0 = lane >> 2, rr1 = rr0 + 8;
            const int cc  = (lane & 3) * 2;
            const int rbase = b * RB;
#pragma unroll
            for (int i = 0; i < 12; i++) {
                const int nt = tw * 12 + i;
                const uint2 B0 = *reinterpret_cast<const uint2*>(
                    wufw + nt * 64 + 2 * lane);
                const uint2 B1 = *reinterpret_cast<const uint2*>(
                    wufw + (96 + nt) * 64 + 2 * lane);
                float c0 = 0, c1 = 0, c2 = 0, c3 = 0;
                mma8(c0, c1, c2, c3, A0.x, A0.y, A0.z, A0.w, B0.x, B0.y);
                mma8(c0, c1, c2, c3, A1.x, A1.y, A1.z, A1.w, B1.x, B1.y);
                const int col = nt * 8 + cc;
                const float2 bu2 = *reinterpret_cast<const float2*>(smp + OFF_BU + col);
                const float2 r0v = *reinterpret_cast<const float2*>(
                    xsb + rr0 * XS_STRIDE + col);
                const float2 r1v = *reinterpret_cast<const float2*>(
                    xsb + rr1 * XS_STRIDE + col);
                float2 o0, o1;
                o0.x = fmaf(0.1f, c0 + bu2.x, r0v.x);
                o0.y = fmaf(0.1f, c1 + bu2.y, r0v.y);
                o1.x = fmaf(0.1f, c2 + bu2.x, r1v.x);
                o1.y = fmaf(0.1f, c3 + bu2.y, r1v.y);
                *reinterpret_cast<float2*>(out + (rbase + rr0) * D_MODEL + col) = o0;
                *reinterpret_cast<float2*>(out + (rbase + rr1) * D_MODEL + col) = o1;
            }
        }
        BAR_SYNC(BID, 256);   // x_s residual reads done before next stage

        b = bn;
    }
}

extern "C" void kernel_launch(void* const* d_in, const int* in_sizes, int n_in,
                              void* d_out, int out_size)
{
    const float* x    = (const float*)d_in[0];
    const float* ln_g = (const float*)d_in[1];
    const float* ln_b = (const float*)d_in[2];
    const float* wd   = (const float*)d_in[3];
    const float* bd   = (const float*)d_in[4];
    const float* wu   = (const float*)d_in[5];
    const float* bu   = (const float*)d_in[6];
    float* out = (float*)d_out;

    cudaFuncSetAttribute(adapter_fused_kernel,
                         cudaFuncAttributeMaxDynamicSharedMemorySize, SMEM_BYTES);
    adapter_fused_kernel<<<GRID, NTHREADS, SMEM_BYTES>>>(x, ln_g, ln_b, wd, bd, wu, bu, out);
}